// round 3
// baseline (speedup 1.0000x reference)
#include <cuda_runtime.h>
#include <math.h>

// Problem constants
#define BB 8
#define TT 2048
#define DD 1024
#define HH 128
#define MM (BB*TT)   // 16384 rows for the QKV GEMM

// Scratch for Q, K, V projections (8 MB each)
__device__ float g_q[BB*TT*HH];
__device__ float g_k[BB*TT*HH];
__device__ float g_v[BB*TT*HH];

// ---------------------------------------------------------------------------
// Kernel 1: QKV projection GEMM.
// C[16384,128] = X[16384,1024] @ W[1024,128], one weight per blockIdx.y.
// 128x128 tile (BN = full N), BK=32, 256 threads, 8x8 microtile.
// ---------------------------------------------------------------------------
__global__ __launch_bounds__(256) void qkv_gemm_kernel(
    const float* __restrict__ x,
    const float* __restrict__ Wq,
    const float* __restrict__ Wk,
    const float* __restrict__ Wv)
{
    const float* W;
    float* out;
    if (blockIdx.y == 0)      { W = Wq; out = g_q; }
    else if (blockIdx.y == 1) { W = Wk; out = g_k; }
    else                      { W = Wv; out = g_v; }

    __shared__ float Xs[32][132];   // [k][m], padded pitch 132 (16B-aligned rows)
    __shared__ float Ws[32][128];   // [k][n]

    const int tid = threadIdx.x;
    const int m0  = blockIdx.x * 128;
    const int ty  = tid / 16;       // 0..15
    const int tx  = tid % 16;       // 0..15

    float acc[8][8];
    #pragma unroll
    for (int i = 0; i < 8; ++i)
        #pragma unroll
        for (int j = 0; j < 8; ++j) acc[i][j] = 0.f;

    const int xr  = tid / 8;         // 0..31
    const int xc4 = (tid % 8) * 4;   // 0..28
    const int wk  = tid / 32;        // 0..7
    const int wn4 = (tid % 32) * 4;  // 0..124

    for (int k0 = 0; k0 < DD; k0 += 32) {
        // Load X tile 128x32 (transposed into Xs)
        #pragma unroll
        for (int p = 0; p < 4; ++p) {
            int m = p * 32 + xr;
            float4 v = *(const float4*)&x[(size_t)(m0 + m) * DD + k0 + xc4];
            Xs[xc4 + 0][m] = v.x;
            Xs[xc4 + 1][m] = v.y;
            Xs[xc4 + 2][m] = v.z;
            Xs[xc4 + 3][m] = v.w;
        }
        // Load W tile 32x128
        #pragma unroll
        for (int p = 0; p < 4; ++p) {
            int kk = p * 8 + wk;
            *(float4*)&Ws[kk][wn4] =
                *(const float4*)&W[(size_t)(k0 + kk) * HH + wn4];
        }
        __syncthreads();

        #pragma unroll
        for (int kk = 0; kk < 32; ++kk) {
            float a[8], b[8];
            #pragma unroll
            for (int i = 0; i < 8; ++i) a[i] = Xs[kk][ty * 8 + i];
            #pragma unroll
            for (int j = 0; j < 8; ++j) b[j] = Ws[kk][tx * 8 + j];
            #pragma unroll
            for (int i = 0; i < 8; ++i)
                #pragma unroll
                for (int j = 0; j < 8; ++j)
                    acc[i][j] += a[i] * b[j];
        }
        __syncthreads();
    }

    #pragma unroll
    for (int i = 0; i < 8; ++i) {
        int m = m0 + ty * 8 + i;
        #pragma unroll
        for (int j = 0; j < 8; j += 4) {
            float4 v = make_float4(acc[i][j], acc[i][j+1], acc[i][j+2], acc[i][j+3]);
            *(float4*)&out[(size_t)m * HH + tx * 8 + j] = v;
        }
    }
}

// ---------------------------------------------------------------------------
// Kernel 2: causal flash attention, fp32, online softmax.
// Grid: 256 CTAs = 8 batches x 32 query tiles of 64 rows, heavy tiles first.
// Block: 256 threads (8 warps). Warp w owns query rows w*8..w*8+7.
// Lane l owns score columns {l, l+32} and output columns {l, l+32, l+64, l+96}.
// ---------------------------------------------------------------------------
#define KTP 65                       // Kt pitch (conflict-free)
#define SMEM_FLOATS (64*128 + 128*KTP + 64*128 + 64*64)

__global__ __launch_bounds__(256) void attn_kernel(float* __restrict__ out)
{
    extern __shared__ float sm[];
    float* Qs = sm;                      // 64 x 128
    float* Kt = Qs + 64 * 128;           // 128 x KTP  (transposed K tile)
    float* Vs = Kt + 128 * KTP;          // 64 x 128
    float* Ps = Vs + 64 * 128;           // 64 x 64

    const int bid   = blockIdx.x;
    const int qtile = 31 - (bid >> 3);   // heavy (late) tiles launch first
    const int b     = bid & 7;
    const int row0  = qtile * 64;

    const float* q = g_q + (size_t)b * TT * HH;
    const float* k = g_k + (size_t)b * TT * HH;
    const float* v = g_v + (size_t)b * TT * HH;

    const int tid = threadIdx.x;
    const int w   = tid >> 5;
    const int l   = tid & 31;
    const int r0w = w * 8;

    // Load Q tile
    for (int i = tid; i < 64 * 32; i += 256) {
        int r  = i >> 5;
        int c4 = (i & 31) * 4;
        *(float4*)&Qs[r * 128 + c4] =
            *(const float4*)&q[(size_t)(row0 + r) * HH + c4];
    }

    float o[8][4];
    float mrow[8], lrow[8];
    #pragma unroll
    for (int r = 0; r < 8; ++r) {
        mrow[r] = -1e30f;
        lrow[r] = 0.f;
        #pragma unroll
        for (int j = 0; j < 4; ++j) o[r][j] = 0.f;
    }

    const float scale = 0.08838834764831845f;   // 1/sqrt(128)

    for (int kt = 0; kt <= qtile; ++kt) {
        const int kr0 = kt * 64;
        __syncthreads();                 // previous PV reads done
        // Load K tile transposed (scalar: coalesced global, conflict-free smem)
        for (int i = tid; i < 64 * 128; i += 256) {
            int c = i >> 7;
            int h = i & 127;
            Kt[h * KTP + c] = k[(size_t)(kr0 + c) * HH + h];
        }
        // Load V tile
        for (int i = tid; i < 64 * 32; i += 256) {
            int c  = i >> 5;
            int h4 = (i & 31) * 4;
            *(float4*)&Vs[c * 128 + h4] =
                *(const float4*)&v[(size_t)(kr0 + c) * HH + h4];
        }
        __syncthreads();

        // S = Q K^T  (per-warp rows, per-lane 2 columns)
        float s0[8], s1[8];
        #pragma unroll
        for (int r = 0; r < 8; ++r) { s0[r] = 0.f; s1[r] = 0.f; }

        #pragma unroll 4
        for (int h = 0; h < 128; ++h) {
            float kv0 = Kt[h * KTP + l];
            float kv1 = Kt[h * KTP + 32 + l];
            #pragma unroll
            for (int r = 0; r < 8; ++r) {
                float qv = Qs[(r0w + r) * 128 + h];
                s0[r] += qv * kv0;
                s1[r] += qv * kv1;
            }
        }

        const bool diag = (kt == qtile);
        #pragma unroll
        for (int r = 0; r < 8; ++r) {
            float a  = s0[r] * scale;
            float bs = s1[r] * scale;
            if (diag) {
                int rg = row0 + r0w + r;
                if (kr0 + l > rg)      a  = -1e30f;
                if (kr0 + 32 + l > rg) bs = -1e30f;
            }
            float tm = fmaxf(a, bs);
            #pragma unroll
            for (int off = 16; off > 0; off >>= 1)
                tm = fmaxf(tm, __shfl_xor_sync(0xffffffffu, tm, off));
            float newm = fmaxf(mrow[r], tm);
            float p0 = __expf(a - newm);
            float p1 = __expf(bs - newm);
            float ps = p0 + p1;
            #pragma unroll
            for (int off = 16; off > 0; off >>= 1)
                ps += __shfl_xor_sync(0xffffffffu, ps, off);
            float corr = __expf(mrow[r] - newm);
            lrow[r] = lrow[r] * corr + ps;
            mrow[r] = newm;
            #pragma unroll
            for (int j = 0; j < 4; ++j) o[r][j] *= corr;
            Ps[(r0w + r) * 64 + l]      = p0;
            Ps[(r0w + r) * 64 + 32 + l] = p1;
        }
        __syncwarp();

        // O += P V
        #pragma unroll 2
        for (int c = 0; c < 64; ++c) {
            float v0 = Vs[c * 128 + l];
            float v1 = Vs[c * 128 + 32 + l];
            float v2 = Vs[c * 128 + 64 + l];
            float v3 = Vs[c * 128 + 96 + l];
            #pragma unroll
            for (int r = 0; r < 8; ++r) {
                float p = Ps[(r0w + r) * 64 + c];
                o[r][0] += p * v0;
                o[r][1] += p * v1;
                o[r][2] += p * v2;
                o[r][3] += p * v3;
            }
        }
    }

    // Epilogue: normalize and store
    float* outp = out + (size_t)b * TT * HH;
    #pragma unroll
    for (int r = 0; r < 8; ++r) {
        float inv = 1.0f / lrow[r];
        size_t base = (size_t)(row0 + r0w + r) * HH;
        outp[base + l]      = o[r][0] * inv;
        outp[base + 32 + l] = o[r][1] * inv;
        outp[base + 64 + l] = o[r][2] * inv;
        outp[base + 96 + l] = o[r][3] * inv;
    }
}

// ---------------------------------------------------------------------------
extern "C" void kernel_launch(void* const* d_in, const int* in_sizes, int n_in,
                              void* d_out, int out_size)
{
    const float* x  = (const float*)d_in[0];
    const float* Wq = (const float*)d_in[1];
    const float* Wk = (const float*)d_in[2];
    const float* Wv = (const float*)d_in[3];
    float* out = (float*)d_out;

    dim3 g1(MM / 128, 3);
    qkv_gemm_kernel<<<g1, 256>>>(x, Wq, Wk, Wv);

    const int smem_bytes = SMEM_FLOATS * (int)sizeof(float);   // 115200 B
    cudaFuncSetAttribute(attn_kernel,
                         cudaFuncAttributeMaxDynamicSharedMemorySize, smem_bytes);
    attn_kernel<<<BB * (TT / 64), 256, smem_bytes>>>(out);
}

// round 5
// speedup vs baseline: 1.2060x; 1.2060x over previous
#include <cuda_runtime.h>
#include <cuda_bf16.h>
#include <cstdint>
#include <math.h>

// Problem constants
#define BB 8
#define TT 2048
#define DD 1024
#define HH 128
#define MM (BB*TT)   // 16384 rows for the QKV GEMM

// Scratch
__device__ float g_q[MM*HH];
__device__ float g_k[MM*HH];
__device__ float g_v[MM*HH];
__device__ __nv_bfloat16 g_xh[MM*DD];   // hi part of X
__device__ __nv_bfloat16 g_xl[MM*DD];   // lo part of X
__device__ __nv_bfloat16 g_wh[3*HH*DD]; // hi part of W, transposed [w][n][k]
__device__ __nv_bfloat16 g_wl[3*HH*DD]; // lo part of W, transposed

// ---------------------------------------------------------------------------
// Warp-MMA helpers (mma.sync bf16 — valid PTX at .target sm_103)
// ---------------------------------------------------------------------------
__device__ __forceinline__ uint32_t smem_u32(const void* p) {
    uint32_t a;
    asm("{ .reg .u64 t; cvta.to.shared.u64 t, %1; cvt.u32.u64 %0, t; }"
        : "=r"(a) : "l"(p));
    return a;
}

__device__ __forceinline__ void ldsm_x4(uint32_t& r0, uint32_t& r1,
                                        uint32_t& r2, uint32_t& r3,
                                        uint32_t addr) {
    asm volatile("ldmatrix.sync.aligned.m8n8.x4.shared.b16 {%0,%1,%2,%3}, [%4];"
                 : "=r"(r0), "=r"(r1), "=r"(r2), "=r"(r3) : "r"(addr));
}

__device__ __forceinline__ void mma_bf16(float* c, const uint32_t* a,
                                         uint32_t b0, uint32_t b1) {
    asm volatile(
        "mma.sync.aligned.m16n8k16.row.col.f32.bf16.bf16.f32 "
        "{%0,%1,%2,%3}, {%4,%5,%6,%7}, {%8,%9}, {%0,%1,%2,%3};"
        : "+f"(c[0]), "+f"(c[1]), "+f"(c[2]), "+f"(c[3])
        : "r"(a[0]), "r"(a[1]), "r"(a[2]), "r"(a[3]), "r"(b0), "r"(b1));
}

// ---------------------------------------------------------------------------
// Kernel 0a: split X (fp32) -> Xh + Xl (bf16)
// ---------------------------------------------------------------------------
__global__ __launch_bounds__(256) void split_x_kernel(const float4* __restrict__ x4)
{
    size_t i = (size_t)blockIdx.x * 256 + threadIdx.x;   // < MM*DD/4
    float4 v = x4[i];
    __nv_bfloat16 h0 = __float2bfloat16(v.x);
    __nv_bfloat16 h1 = __float2bfloat16(v.y);
    __nv_bfloat16 h2 = __float2bfloat16(v.z);
    __nv_bfloat16 h3 = __float2bfloat16(v.w);
    __nv_bfloat16 l0 = __float2bfloat16(v.x - __bfloat162float(h0));
    __nv_bfloat16 l1 = __float2bfloat16(v.y - __bfloat162float(h1));
    __nv_bfloat16 l2 = __float2bfloat16(v.z - __bfloat162float(h2));
    __nv_bfloat16 l3 = __float2bfloat16(v.w - __bfloat162float(h3));
    __nv_bfloat162* xh2 = (__nv_bfloat162*)g_xh;
    __nv_bfloat162* xl2 = (__nv_bfloat162*)g_xl;
    xh2[i * 2]     = __halves2bfloat162(h0, h1);
    xh2[i * 2 + 1] = __halves2bfloat162(h2, h3);
    xl2[i * 2]     = __halves2bfloat162(l0, l1);
    xl2[i * 2 + 1] = __halves2bfloat162(l2, l3);
}

// ---------------------------------------------------------------------------
// Kernel 0b: split + transpose W -> Wh_t, Wl_t  ([w][n][k], bf16)
// ---------------------------------------------------------------------------
__global__ __launch_bounds__(256) void split_w_kernel(
    const float* __restrict__ Wq,
    const float* __restrict__ Wk,
    const float* __restrict__ Wv)
{
    int i = blockIdx.x * 256 + threadIdx.x;   // < 3*DD*HH
    int widx = i / (DD * HH);
    int rem  = i - widx * DD * HH;
    int k = rem / HH;
    int n = rem % HH;
    const float* W = (widx == 0) ? Wq : (widx == 1) ? Wk : Wv;
    float v = W[k * HH + n];
    __nv_bfloat16 h = __float2bfloat16(v);
    __nv_bfloat16 l = __float2bfloat16(v - __bfloat162float(h));
    size_t dst = (size_t)widx * HH * DD + (size_t)n * DD + k;
    g_wh[dst] = h;
    g_wl[dst] = l;
}

// ---------------------------------------------------------------------------
// Kernel 1: QKV GEMM via mma.sync bf16-split (3 products: AhBh+AhBl+AlBh).
// C[16384,128] = X @ W. Grid (128 Mtiles, 3 weights), 256 threads = 8 warps
// arranged 4(M) x 2(N); warp tile m32 x n64; BK=32.
// Smem tiles 128x32 bf16 at pitch 40 elems (80 B rows -> conflict-free ldmatrix).
// ---------------------------------------------------------------------------
#define PITCH 40

__global__ __launch_bounds__(256) void qkv_mma_kernel()
{
    __shared__ __align__(16) __nv_bfloat16 sAh[128 * PITCH];
    __shared__ __align__(16) __nv_bfloat16 sAl[128 * PITCH];
    __shared__ __align__(16) __nv_bfloat16 sBh[128 * PITCH];
    __shared__ __align__(16) __nv_bfloat16 sBl[128 * PITCH];

    const int tid  = threadIdx.x;
    const int wid  = tid >> 5;
    const int lane = tid & 31;
    const int m0   = blockIdx.x * 128;
    const int widx = blockIdx.y;

    const __nv_bfloat16* xh = g_xh + (size_t)m0 * DD;
    const __nv_bfloat16* xl = g_xl + (size_t)m0 * DD;
    const __nv_bfloat16* wh = g_wh + (size_t)widx * HH * DD;
    const __nv_bfloat16* wl = g_wl + (size_t)widx * HH * DD;
    float* out = (widx == 0) ? g_q : (widx == 1) ? g_k : g_v;

    const int warp_m0 = (wid & 3) * 32;    // 0,32,64,96
    const int warp_n0 = (wid >> 2) * 64;   // 0,64

    float acc[2][8][4];
    #pragma unroll
    for (int m = 0; m < 2; ++m)
        #pragma unroll
        for (int j = 0; j < 8; ++j)
            #pragma unroll
            for (int e = 0; e < 4; ++e) acc[m][j][e] = 0.f;

    // smem-load indexing: 128 rows x 32 cols, 4 x uint4 per row, 512 uint4/tile
    const int lrow0 = tid >> 2;          // 0..63
    const int lseg  = (tid & 3) * 8;     // 0,8,16,24 (elements)

    // ldmatrix addresses (per k16-step s add s*32 bytes)
    const uint32_t aBase = smem_u32(sAh);
    const uint32_t bBase = smem_u32(sBh);
    const uint32_t alBase = smem_u32(sAl);
    const uint32_t blBase = smem_u32(sBl);
    const int frag_row = lane & 15;
    const int frag_col = (lane >> 4) * 8;

    for (int c = 0; c < 32; ++c) {
        const int k0 = c * 32;
        // Load 4 tiles (2 x uint4 per thread per tile)
        #pragma unroll
        for (int h = 0; h < 2; ++h) {
            int row = lrow0 + h * 64;
            size_t gsrc = (size_t)row * DD + k0 + lseg;
            uint32_t dst = (uint32_t)row * PITCH + lseg;
            *(uint4*)&sAh[dst] = *(const uint4*)&xh[gsrc];
            *(uint4*)&sAl[dst] = *(const uint4*)&xl[gsrc];
            *(uint4*)&sBh[dst] = *(const uint4*)&wh[gsrc];
            *(uint4*)&sBl[dst] = *(const uint4*)&wl[gsrc];
        }
        __syncthreads();

        #pragma unroll
        for (int s = 0; s < 2; ++s) {
            const uint32_t colOff = (uint32_t)(s * 16 + frag_col) * 2;
            uint32_t ah[2][4], al[2][4], bh[4][4], bl[4][4];
            #pragma unroll
            for (int m = 0; m < 2; ++m) {
                uint32_t ro = (uint32_t)(warp_m0 + m * 16 + frag_row) * (PITCH * 2);
                ldsm_x4(ah[m][0], ah[m][1], ah[m][2], ah[m][3], aBase + ro + colOff);
                ldsm_x4(al[m][0], al[m][1], al[m][2], al[m][3], alBase + ro + colOff);
            }
            #pragma unroll
            for (int g = 0; g < 4; ++g) {
                uint32_t ro = (uint32_t)(warp_n0 + g * 16 + frag_row) * (PITCH * 2);
                ldsm_x4(bh[g][0], bh[g][1], bh[g][2], bh[g][3], bBase + ro + colOff);
                ldsm_x4(bl[g][0], bl[g][1], bl[g][2], bl[g][3], blBase + ro + colOff);
            }
            #pragma unroll
            for (int m = 0; m < 2; ++m) {
                #pragma unroll
                for (int g = 0; g < 4; ++g) {
                    // n8 pair within this n16 group
                    mma_bf16(acc[m][2*g],   ah[m], bh[g][0], bh[g][2]);
                    mma_bf16(acc[m][2*g+1], ah[m], bh[g][1], bh[g][3]);
                    mma_bf16(acc[m][2*g],   ah[m], bl[g][0], bl[g][2]);
                    mma_bf16(acc[m][2*g+1], ah[m], bl[g][1], bl[g][3]);
                    mma_bf16(acc[m][2*g],   al[m], bh[g][0], bh[g][2]);
                    mma_bf16(acc[m][2*g+1], al[m], bh[g][1], bh[g][3]);
                }
            }
        }
        __syncthreads();
    }

    // Epilogue
    #pragma unroll
    for (int m = 0; m < 2; ++m) {
        int rr = m0 + warp_m0 + m * 16 + (lane >> 2);
        #pragma unroll
        for (int j = 0; j < 8; ++j) {
            int cc = warp_n0 + j * 8 + (lane & 3) * 2;
            *(float2*)&out[(size_t)rr * HH + cc] =
                make_float2(acc[m][j][0], acc[m][j][1]);
            *(float2*)&out[(size_t)(rr + 8) * HH + cc] =
                make_float2(acc[m][j][2], acc[m][j][3]);
        }
    }
}

// ---------------------------------------------------------------------------
// Kernel 2: causal flash attention, fp32, online softmax.
// Grid: 256 CTAs = 8 batches x 32 query tiles of 64 rows, heavy tiles first.
// Block: 256 threads (8 warps). Warp w owns query rows w*8..w*8+7.
// Lane l owns score columns {l, l+32} and output columns {l, l+32, l+64, l+96}.
// QK unrolled h x4 with float4 broadcast Q loads; PV unrolled c x4 with float4
// broadcast P loads -> both phases FFMA-issue-dominated.
// ---------------------------------------------------------------------------
#define KTP 65                       // Kt pitch (conflict-free)
#define SMEM_FLOATS (64*128 + 128*KTP + 64*128 + 64*64)

__global__ __launch_bounds__(256) void attn_kernel(float* __restrict__ out)
{
    extern __shared__ float sm[];
    float* Qs = sm;                      // 64 x 128
    float* Kt = Qs + 64 * 128;           // 128 x KTP  (transposed K tile)
    float* Vs = Kt + 128 * KTP;          // 64 x 128
    float* Ps = Vs + 64 * 128;           // 64 x 64

    const int bid   = blockIdx.x;
    const int qtile = 31 - (bid >> 3);   // heavy (late) tiles launch first
    const int b     = bid & 7;
    const int row0  = qtile * 64;

    const float* q = g_q + (size_t)b * TT * HH;
    const float* k = g_k + (size_t)b * TT * HH;
    const float* v = g_v + (size_t)b * TT * HH;

    const int tid = threadIdx.x;
    const int w   = tid >> 5;
    const int l   = tid & 31;
    const int r0w = w * 8;

    // Load Q tile
    for (int i = tid; i < 64 * 32; i += 256) {
        int r  = i >> 5;
        int c4 = (i & 31) * 4;
        *(float4*)&Qs[r * 128 + c4] =
            *(const float4*)&q[(size_t)(row0 + r) * HH + c4];
    }

    float o[8][4];
    float mrow[8], lrow[8];
    #pragma unroll
    for (int r = 0; r < 8; ++r) {
        mrow[r] = -1e30f;
        lrow[r] = 0.f;
        #pragma unroll
        for (int j = 0; j < 4; ++j) o[r][j] = 0.f;
    }

    const float scale = 0.08838834764831845f;   // 1/sqrt(128)

    for (int kt = 0; kt <= qtile; ++kt) {
        const int kr0 = kt * 64;
        __syncthreads();                 // previous PV reads done
        // Load K tile transposed (coalesced global, conflict-free smem)
        for (int i = tid; i < 64 * 128; i += 256) {
            int c = i >> 7;
            int h = i & 127;
            Kt[h * KTP + c] = k[(size_t)(kr0 + c) * HH + h];
        }
        // Load V tile
        for (int i = tid; i < 64 * 32; i += 256) {
            int c  = i >> 5;
            int h4 = (i & 31) * 4;
            *(float4*)&Vs[c * 128 + h4] =
                *(const float4*)&v[(size_t)(kr0 + c) * HH + h4];
        }
        __syncthreads();

        // S = Q K^T  (per-warp rows, per-lane 2 columns), h unrolled x4
        float s0[8], s1[8];
        #pragma unroll
        for (int r = 0; r < 8; ++r) { s0[r] = 0.f; s1[r] = 0.f; }

        #pragma unroll 2
        for (int h = 0; h < 128; h += 4) {
            float k00 = Kt[(h + 0) * KTP + l];
            float k01 = Kt[(h + 1) * KTP + l];
            float k02 = Kt[(h + 2) * KTP + l];
            float k03 = Kt[(h + 3) * KTP + l];
            float k10 = Kt[(h + 0) * KTP + 32 + l];
            float k11 = Kt[(h + 1) * KTP + 32 + l];
            float k12 = Kt[(h + 2) * KTP + 32 + l];
            float k13 = Kt[(h + 3) * KTP + 32 + l];
            #pragma unroll
            for (int r = 0; r < 8; ++r) {
                float4 q4 = *(const float4*)&Qs[(r0w + r) * 128 + h];
                s0[r] += q4.x * k00 + q4.y * k01 + q4.z * k02 + q4.w * k03;
                s1[r] += q4.x * k10 + q4.y * k11 + q4.z * k12 + q4.w * k13;
            }
        }

        const bool diag = (kt == qtile);
        #pragma unroll
        for (int r = 0; r < 8; ++r) {
            float a  = s0[r] * scale;
            float bs = s1[r] * scale;
            if (diag) {
                int rg = row0 + r0w + r;
                if (kr0 + l > rg)      a  = -1e30f;
                if (kr0 + 32 + l > rg) bs = -1e30f;
            }
            float tm = fmaxf(a, bs);
            #pragma unroll
            for (int off = 16; off > 0; off >>= 1)
                tm = fmaxf(tm, __shfl_xor_sync(0xffffffffu, tm, off));
            float newm = fmaxf(mrow[r], tm);
            float p0 = __expf(a - newm);
            float p1 = __expf(bs - newm);
            float ps = p0 + p1;
            #pragma unroll
            for (int off = 16; off > 0; off >>= 1)
                ps += __shfl_xor_sync(0xffffffffu, ps, off);
            float corr = __expf(mrow[r] - newm);
            lrow[r] = lrow[r] * corr + ps;
            mrow[r] = newm;
            #pragma unroll
            for (int j = 0; j < 4; ++j) o[r][j] *= corr;
            Ps[(r0w + r) * 64 + l]      = p0;
            Ps[(r0w + r) * 64 + 32 + l] = p1;
        }
        __syncwarp();

        // O += P V, c unrolled x4 with float4 broadcast P loads
        #pragma unroll 1
        for (int c = 0; c < 64; c += 4) {
            float v0x = Vs[(c + 0) * 128 + l];
            float v0y = Vs[(c + 1) * 128 + l];
            float v0z = Vs[(c + 2) * 128 + l];
            float v0w = Vs[(c + 3) * 128 + l];
            float v1x = Vs[(c + 0) * 128 + 32 + l];
            float v1y = Vs[(c + 1) * 128 + 32 + l];
            float v1z = Vs[(c + 2) * 128 + 32 + l];
            float v1w = Vs[(c + 3) * 128 + 32 + l];
            float v2x = Vs[(c + 0) * 128 + 64 + l];
            float v2y = Vs[(c + 1) * 128 + 64 + l];
            float v2z = Vs[(c + 2) * 128 + 64 + l];
            float v2w = Vs[(c + 3) * 128 + 64 + l];
            float v3x = Vs[(c + 0) * 128 + 96 + l];
            float v3y = Vs[(c + 1) * 128 + 96 + l];
            float v3z = Vs[(c + 2) * 128 + 96 + l];
            float v3w = Vs[(c + 3) * 128 + 96 + l];
            #pragma unroll
            for (int r = 0; r < 8; ++r) {
                float4 p4 = *(const float4*)&Ps[(r0w + r) * 64 + c];
                o[r][0] += p4.x * v0x + p4.y * v0y + p4.z * v0z + p4.w * v0w;
                o[r][1] += p4.x * v1x + p4.y * v1y + p4.z * v1z + p4.w * v1w;
                o[r][2] += p4.x * v2x + p4.y * v2y + p4.z * v2z + p4.w * v2w;
                o[r][3] += p4.x * v3x + p4.y * v3y + p4.z * v3z + p4.w * v3w;
            }
        }
    }

    // Epilogue: normalize and store
    float* outp = out + (size_t)b * TT * HH;
    #pragma unroll
    for (int r = 0; r < 8; ++r) {
        float inv = 1.0f / lrow[r];
        size_t base = (size_t)(row0 + r0w + r) * HH;
        outp[base + l]      = o[r][0] * inv;
        outp[base + 32 + l] = o[r][1] * inv;
        outp[base + 64 + l] = o[r][2] * inv;
        outp[base + 96 + l] = o[r][3] * inv;
    }
}

// ---------------------------------------------------------------------------
extern "C" void kernel_launch(void* const* d_in, const int* in_sizes, int n_in,
                              void* d_out, int out_size)
{
    const float* x  = (const float*)d_in[0];
    const float* Wq = (const float*)d_in[1];
    const float* Wk = (const float*)d_in[2];
    const float* Wv = (const float*)d_in[3];
    float* out = (float*)d_out;

    // Split inputs into bf16 hi/lo
    split_x_kernel<<<MM * DD / 4 / 256, 256>>>((const float4*)x);
    split_w_kernel<<<3 * DD * HH / 256, 256>>>(Wq, Wk, Wv);

    // QKV projection on tensor cores (mma.sync bf16-split)
    dim3 gm(MM / 128, 3);
    qkv_mma_kernel<<<gm, 256>>>();

    // Attention
    const int smem_bytes = SMEM_FLOATS * (int)sizeof(float);   // 115200 B
    cudaFuncSetAttribute(attn_kernel,
                         cudaFuncAttributeMaxDynamicSharedMemorySize, smem_bytes);
    attn_kernel<<<BB * (TT / 64), 256, smem_bytes>>>(out);
}

// round 6
// speedup vs baseline: 1.5759x; 1.3067x over previous
#include <cuda_runtime.h>
#include <cuda_bf16.h>
#include <cstdint>
#include <math.h>

// Problem constants
#define BB 8
#define TT 2048
#define DD 1024
#define HH 128
#define MM (BB*TT)   // 16384 rows for the QKV GEMM

// Scratch: Q/K/V as bf16 hi/lo splits (Q has softmax scale folded in)
__device__ __nv_bfloat16 g_qh[MM*HH];
__device__ __nv_bfloat16 g_ql[MM*HH];
__device__ __nv_bfloat16 g_kh[MM*HH];
__device__ __nv_bfloat16 g_kl[MM*HH];
__device__ __nv_bfloat16 g_vh[MM*HH];
__device__ __nv_bfloat16 g_vl[MM*HH];
__device__ __nv_bfloat16 g_xh[MM*DD];   // hi part of X
__device__ __nv_bfloat16 g_xl[MM*DD];   // lo part of X
__device__ __nv_bfloat16 g_wh[3*HH*DD]; // hi part of W, transposed [w][n][k]
__device__ __nv_bfloat16 g_wl[3*HH*DD]; // lo part of W, transposed

// ---------------------------------------------------------------------------
// Warp-MMA helpers (mma.sync bf16 — valid PTX at .target sm_103)
// ---------------------------------------------------------------------------
__device__ __forceinline__ uint32_t smem_u32(const void* p) {
    uint32_t a;
    asm("{ .reg .u64 t; cvta.to.shared.u64 t, %1; cvt.u32.u64 %0, t; }"
        : "=r"(a) : "l"(p));
    return a;
}

__device__ __forceinline__ void ldsm_x4(uint32_t& r0, uint32_t& r1,
                                        uint32_t& r2, uint32_t& r3,
                                        uint32_t addr) {
    asm volatile("ldmatrix.sync.aligned.m8n8.x4.shared.b16 {%0,%1,%2,%3}, [%4];"
                 : "=r"(r0), "=r"(r1), "=r"(r2), "=r"(r3) : "r"(addr));
}

__device__ __forceinline__ void ldsm_x4_t(uint32_t& r0, uint32_t& r1,
                                          uint32_t& r2, uint32_t& r3,
                                          uint32_t addr) {
    asm volatile("ldmatrix.sync.aligned.m8n8.x4.trans.shared.b16 {%0,%1,%2,%3}, [%4];"
                 : "=r"(r0), "=r"(r1), "=r"(r2), "=r"(r3) : "r"(addr));
}

__device__ __forceinline__ void mma_bf16(float* c, const uint32_t* a,
                                         uint32_t b0, uint32_t b1) {
    asm volatile(
        "mma.sync.aligned.m16n8k16.row.col.f32.bf16.bf16.f32 "
        "{%0,%1,%2,%3}, {%4,%5,%6,%7}, {%8,%9}, {%0,%1,%2,%3};"
        : "+f"(c[0]), "+f"(c[1]), "+f"(c[2]), "+f"(c[3])
        : "r"(a[0]), "r"(a[1]), "r"(a[2]), "r"(a[3]), "r"(b0), "r"(b1));
}

__device__ __forceinline__ uint32_t pack_bf16x2(float a, float b) {
    __nv_bfloat162 p = __halves2bfloat162(__float2bfloat16(a), __float2bfloat16(b));
    return *(uint32_t*)&p;
}

// ---------------------------------------------------------------------------
// Kernel 0a: split X (fp32) -> Xh + Xl (bf16)
// ---------------------------------------------------------------------------
__global__ __launch_bounds__(256) void split_x_kernel(const float4* __restrict__ x4)
{
    size_t i = (size_t)blockIdx.x * 256 + threadIdx.x;   // < MM*DD/4
    float4 v = x4[i];
    __nv_bfloat16 h0 = __float2bfloat16(v.x);
    __nv_bfloat16 h1 = __float2bfloat16(v.y);
    __nv_bfloat16 h2 = __float2bfloat16(v.z);
    __nv_bfloat16 h3 = __float2bfloat16(v.w);
    __nv_bfloat16 l0 = __float2bfloat16(v.x - __bfloat162float(h0));
    __nv_bfloat16 l1 = __float2bfloat16(v.y - __bfloat162float(h1));
    __nv_bfloat16 l2 = __float2bfloat16(v.z - __bfloat162float(h2));
    __nv_bfloat16 l3 = __float2bfloat16(v.w - __bfloat162float(h3));
    __nv_bfloat162* xh2 = (__nv_bfloat162*)g_xh;
    __nv_bfloat162* xl2 = (__nv_bfloat162*)g_xl;
    xh2[i * 2]     = __halves2bfloat162(h0, h1);
    xh2[i * 2 + 1] = __halves2bfloat162(h2, h3);
    xl2[i * 2]     = __halves2bfloat162(l0, l1);
    xl2[i * 2 + 1] = __halves2bfloat162(l2, l3);
}

// ---------------------------------------------------------------------------
// Kernel 0b: split + transpose W -> Wh_t, Wl_t  ([w][n][k], bf16)
// ---------------------------------------------------------------------------
__global__ __launch_bounds__(256) void split_w_kernel(
    const float* __restrict__ Wq,
    const float* __restrict__ Wk,
    const float* __restrict__ Wv)
{
    int i = blockIdx.x * 256 + threadIdx.x;   // < 3*DD*HH
    int widx = i / (DD * HH);
    int rem  = i - widx * DD * HH;
    int k = rem / HH;
    int n = rem % HH;
    const float* W = (widx == 0) ? Wq : (widx == 1) ? Wk : Wv;
    float v = W[k * HH + n];
    __nv_bfloat16 h = __float2bfloat16(v);
    __nv_bfloat16 l = __float2bfloat16(v - __bfloat162float(h));
    size_t dst = (size_t)widx * HH * DD + (size_t)n * DD + k;
    g_wh[dst] = h;
    g_wl[dst] = l;
}

// ---------------------------------------------------------------------------
// Kernel 1: QKV GEMM via mma.sync bf16-split (3 products: AhBh+AhBl+AlBh).
// Epilogue writes bf16 hi/lo Q/K/V (scale folded into Q).
// ---------------------------------------------------------------------------
#define PITCH 40

__global__ __launch_bounds__(256) void qkv_mma_kernel()
{
    __shared__ __align__(16) __nv_bfloat16 sAh[128 * PITCH];
    __shared__ __align__(16) __nv_bfloat16 sAl[128 * PITCH];
    __shared__ __align__(16) __nv_bfloat16 sBh[128 * PITCH];
    __shared__ __align__(16) __nv_bfloat16 sBl[128 * PITCH];

    const int tid  = threadIdx.x;
    const int wid  = tid >> 5;
    const int lane = tid & 31;
    const int m0   = blockIdx.x * 128;
    const int widx = blockIdx.y;

    const __nv_bfloat16* xh = g_xh + (size_t)m0 * DD;
    const __nv_bfloat16* xl = g_xl + (size_t)m0 * DD;
    const __nv_bfloat16* wh = g_wh + (size_t)widx * HH * DD;
    const __nv_bfloat16* wl = g_wl + (size_t)widx * HH * DD;
    __nv_bfloat16* outh = (widx == 0) ? g_qh : (widx == 1) ? g_kh : g_vh;
    __nv_bfloat16* outl = (widx == 0) ? g_ql : (widx == 1) ? g_kl : g_vl;
    const float sc = (widx == 0) ? 0.08838834764831845f : 1.0f;

    const int warp_m0 = (wid & 3) * 32;    // 0,32,64,96
    const int warp_n0 = (wid >> 2) * 64;   // 0,64

    float acc[2][8][4];
    #pragma unroll
    for (int m = 0; m < 2; ++m)
        #pragma unroll
        for (int j = 0; j < 8; ++j)
            #pragma unroll
            for (int e = 0; e < 4; ++e) acc[m][j][e] = 0.f;

    const int lrow0 = tid >> 2;          // 0..63
    const int lseg  = (tid & 3) * 8;     // 0,8,16,24 (elements)

    const uint32_t aBase  = smem_u32(sAh);
    const uint32_t bBase  = smem_u32(sBh);
    const uint32_t alBase = smem_u32(sAl);
    const uint32_t blBase = smem_u32(sBl);
    const int frag_row = lane & 15;
    const int frag_col = (lane >> 4) * 8;

    for (int c = 0; c < 32; ++c) {
        const int k0 = c * 32;
        #pragma unroll
        for (int h = 0; h < 2; ++h) {
            int row = lrow0 + h * 64;
            size_t gsrc = (size_t)row * DD + k0 + lseg;
            uint32_t dst = (uint32_t)row * PITCH + lseg;
            *(uint4*)&sAh[dst] = *(const uint4*)&xh[gsrc];
            *(uint4*)&sAl[dst] = *(const uint4*)&xl[gsrc];
            *(uint4*)&sBh[dst] = *(const uint4*)&wh[gsrc];
            *(uint4*)&sBl[dst] = *(const uint4*)&wl[gsrc];
        }
        __syncthreads();

        #pragma unroll
        for (int s = 0; s < 2; ++s) {
            const uint32_t colOff = (uint32_t)(s * 16 + frag_col) * 2;
            uint32_t ah[2][4], al[2][4], bh[4][4], bl[4][4];
            #pragma unroll
            for (int m = 0; m < 2; ++m) {
                uint32_t ro = (uint32_t)(warp_m0 + m * 16 + frag_row) * (PITCH * 2);
                ldsm_x4(ah[m][0], ah[m][1], ah[m][2], ah[m][3], aBase + ro + colOff);
                ldsm_x4(al[m][0], al[m][1], al[m][2], al[m][3], alBase + ro + colOff);
            }
            #pragma unroll
            for (int g = 0; g < 4; ++g) {
                uint32_t ro = (uint32_t)(warp_n0 + g * 16 + frag_row) * (PITCH * 2);
                ldsm_x4(bh[g][0], bh[g][1], bh[g][2], bh[g][3], bBase + ro + colOff);
                ldsm_x4(bl[g][0], bl[g][1], bl[g][2], bl[g][3], blBase + ro + colOff);
            }
            #pragma unroll
            for (int m = 0; m < 2; ++m) {
                #pragma unroll
                for (int g = 0; g < 4; ++g) {
                    mma_bf16(acc[m][2*g],   ah[m], bh[g][0], bh[g][2]);
                    mma_bf16(acc[m][2*g+1], ah[m], bh[g][1], bh[g][3]);
                    mma_bf16(acc[m][2*g],   ah[m], bl[g][0], bl[g][2]);
                    mma_bf16(acc[m][2*g+1], ah[m], bl[g][1], bl[g][3]);
                    mma_bf16(acc[m][2*g],   al[m], bh[g][0], bh[g][2]);
                    mma_bf16(acc[m][2*g+1], al[m], bh[g][1], bh[g][3]);
                }
            }
        }
        __syncthreads();
    }

    // Epilogue: split fp32 accum -> bf16 hi/lo, write both
    #pragma unroll
    for (int m = 0; m < 2; ++m) {
        int rr = m0 + warp_m0 + m * 16 + (lane >> 2);
        #pragma unroll
        for (int j = 0; j < 8; ++j) {
            int cc = warp_n0 + j * 8 + (lane & 3) * 2;
            #pragma unroll
            for (int half = 0; half < 2; ++half) {
                float v0 = acc[m][j][half * 2]     * sc;
                float v1 = acc[m][j][half * 2 + 1] * sc;
                __nv_bfloat16 h0 = __float2bfloat16(v0);
                __nv_bfloat16 h1 = __float2bfloat16(v1);
                __nv_bfloat16 l0 = __float2bfloat16(v0 - __bfloat162float(h0));
                __nv_bfloat16 l1 = __float2bfloat16(v1 - __bfloat162float(h1));
                size_t off = (size_t)(rr + half * 8) * HH + cc;
                *(__nv_bfloat162*)&outh[off] = __halves2bfloat162(h0, h1);
                *(__nv_bfloat162*)&outl[off] = __halves2bfloat162(l0, l1);
            }
        }
    }
}

// ---------------------------------------------------------------------------
// Kernel 2: causal flash attention on tensor cores (mma.sync bf16-split).
// Grid: 256 CTAs = 8 batches x 32 query tiles of 64 rows, heavy tiles first.
// Block: 128 threads (4 warps); warp w owns Q rows w*16..w*16+15.
// Q fragments register-resident (hi/lo). S and O accumulate in fp32 fragments.
// P is repacked from C-layout to A-layout in registers (FA2 identity) with
// hi/lo split; V fragments via ldmatrix.trans.
// ---------------------------------------------------------------------------
#define APITCH 136            // smem tile pitch in bf16 elems (272B: conflict-free)
#define ATT_SMEM (4 * 64 * APITCH * 2)   // Kh,Kl,Vh,Vl

__global__ __launch_bounds__(128) void attn_kernel(float* __restrict__ out)
{
    extern __shared__ __nv_bfloat16 smb[];
    __nv_bfloat16* Kh = smb;
    __nv_bfloat16* Kl = Kh + 64 * APITCH;
    __nv_bfloat16* Vh = Kl + 64 * APITCH;
    __nv_bfloat16* Vl = Vh + 64 * APITCH;

    const int bid   = blockIdx.x;
    const int qtile = 31 - (bid >> 3);   // heavy (late) tiles launch first
    const int b     = bid & 7;
    const int row0  = qtile * 64;

    const __nv_bfloat16* qhp = g_qh + (size_t)b * TT * HH;
    const __nv_bfloat16* qlp = g_ql + (size_t)b * TT * HH;
    const __nv_bfloat16* khp = g_kh + (size_t)b * TT * HH;
    const __nv_bfloat16* klp = g_kl + (size_t)b * TT * HH;
    const __nv_bfloat16* vhp = g_vh + (size_t)b * TT * HH;
    const __nv_bfloat16* vlp = g_vl + (size_t)b * TT * HH;

    const int tid  = threadIdx.x;
    const int warp = tid >> 5;
    const int lane = tid & 31;

    const uint32_t KhB = smem_u32(Kh);
    const uint32_t KlB = smem_u32(Kl);
    const uint32_t VhB = smem_u32(Vh);
    const uint32_t VlB = smem_u32(Vl);
    const int frag_row = lane & 15;
    const int frag_col = (lane >> 4) * 8;

    // ---- Stage Q tile (hi into Kh, lo into Kl), load fragments, release ----
    for (int i = tid; i < 64 * 16; i += 128) {
        int r = i >> 4, seg = (i & 15) * 8;
        *(uint4*)&Kh[r * APITCH + seg] = *(const uint4*)&qhp[(size_t)(row0 + r) * HH + seg];
        *(uint4*)&Kl[r * APITCH + seg] = *(const uint4*)&qlp[(size_t)(row0 + r) * HH + seg];
    }
    __syncthreads();

    uint32_t qh[8][4], ql[8][4];
    {
        uint32_t ro = (uint32_t)(warp * 16 + frag_row) * (APITCH * 2);
        #pragma unroll
        for (int g = 0; g < 8; ++g) {
            uint32_t co = (uint32_t)(g * 16 + frag_col) * 2;
            ldsm_x4(qh[g][0], qh[g][1], qh[g][2], qh[g][3], KhB + ro + co);
            ldsm_x4(ql[g][0], ql[g][1], ql[g][2], ql[g][3], KlB + ro + co);
        }
    }

    float o[16][4];
    #pragma unroll
    for (int j = 0; j < 16; ++j)
        #pragma unroll
        for (int e = 0; e < 4; ++e) o[j][e] = 0.f;
    float m0 = -1e30f, m1 = -1e30f, l0 = 0.f, l1 = 0.f;

    const int r0g = row0 + warp * 16 + (lane >> 2);   // global row (thread)
    const int r1g = r0g + 8;

    for (int kt = 0; kt <= qtile; ++kt) {
        const int kr0 = kt * 64;
        __syncthreads();      // everyone done reading smem from prev iter
        for (int i = tid; i < 64 * 16; i += 128) {
            int r = i >> 4, seg = (i & 15) * 8;
            size_t gs = (size_t)(kr0 + r) * HH + seg;
            uint32_t ds = (uint32_t)r * APITCH + seg;
            *(uint4*)&Kh[ds] = *(const uint4*)&khp[gs];
            *(uint4*)&Kl[ds] = *(const uint4*)&klp[gs];
            *(uint4*)&Vh[ds] = *(const uint4*)&vhp[gs];
            *(uint4*)&Vl[ds] = *(const uint4*)&vlp[gs];
        }
        __syncthreads();

        // ---- S = Q K^T (scaled; scale folded into Q) ----
        float s[8][4];
        #pragma unroll
        for (int j = 0; j < 8; ++j)
            #pragma unroll
            for (int e = 0; e < 4; ++e) s[j][e] = 0.f;

        #pragma unroll
        for (int g = 0; g < 8; ++g) {             // k16 step over head dim
            const uint32_t co = (uint32_t)(g * 16 + frag_col) * 2;
            #pragma unroll
            for (int n = 0; n < 4; ++n) {         // n16 group over seq
                uint32_t ro = (uint32_t)(n * 16 + frag_row) * (APITCH * 2);
                uint32_t b0, b1, b2, b3, c0, c1, c2, c3;
                ldsm_x4(b0, b1, b2, b3, KhB + ro + co);
                ldsm_x4(c0, c1, c2, c3, KlB + ro + co);
                mma_bf16(s[2*n],   qh[g], b0, b2);
                mma_bf16(s[2*n+1], qh[g], b1, b3);
                mma_bf16(s[2*n],   qh[g], c0, c2);
                mma_bf16(s[2*n+1], qh[g], c1, c3);
                mma_bf16(s[2*n],   ql[g], b0, b2);
                mma_bf16(s[2*n+1], ql[g], b1, b3);
            }
        }

        // ---- Causal mask (diagonal tile only) ----
        if (kt == qtile) {
            const int c0 = kr0 + (lane & 3) * 2;
            #pragma unroll
            for (int j = 0; j < 8; ++j) {
                int cg = c0 + j * 8;
                if (cg     > r0g) s[j][0] = -1e30f;
                if (cg + 1 > r0g) s[j][1] = -1e30f;
                if (cg     > r1g) s[j][2] = -1e30f;
                if (cg + 1 > r1g) s[j][3] = -1e30f;
            }
        }

        // ---- Online softmax on fragments ----
        float mx0 = -1e30f, mx1 = -1e30f;
        #pragma unroll
        for (int j = 0; j < 8; ++j) {
            mx0 = fmaxf(mx0, fmaxf(s[j][0], s[j][1]));
            mx1 = fmaxf(mx1, fmaxf(s[j][2], s[j][3]));
        }
        mx0 = fmaxf(mx0, __shfl_xor_sync(0xffffffffu, mx0, 1));
        mx0 = fmaxf(mx0, __shfl_xor_sync(0xffffffffu, mx0, 2));
        mx1 = fmaxf(mx1, __shfl_xor_sync(0xffffffffu, mx1, 1));
        mx1 = fmaxf(mx1, __shfl_xor_sync(0xffffffffu, mx1, 2));
        const float nm0 = fmaxf(m0, mx0);
        const float nm1 = fmaxf(m1, mx1);
        float sum0 = 0.f, sum1 = 0.f;
        #pragma unroll
        for (int j = 0; j < 8; ++j) {
            s[j][0] = __expf(s[j][0] - nm0);
            s[j][1] = __expf(s[j][1] - nm0);
            s[j][2] = __expf(s[j][2] - nm1);
            s[j][3] = __expf(s[j][3] - nm1);
            sum0 += s[j][0] + s[j][1];
            sum1 += s[j][2] + s[j][3];
        }
        sum0 += __shfl_xor_sync(0xffffffffu, sum0, 1);
        sum0 += __shfl_xor_sync(0xffffffffu, sum0, 2);
        sum1 += __shfl_xor_sync(0xffffffffu, sum1, 1);
        sum1 += __shfl_xor_sync(0xffffffffu, sum1, 2);
        const float cr0 = __expf(m0 - nm0);
        const float cr1 = __expf(m1 - nm1);
        l0 = l0 * cr0 + sum0;
        l1 = l1 * cr1 + sum1;
        m0 = nm0; m1 = nm1;
        #pragma unroll
        for (int j = 0; j < 16; ++j) {
            o[j][0] *= cr0; o[j][1] *= cr0;
            o[j][2] *= cr1; o[j][3] *= cr1;
        }

        // ---- O += P V ----
        #pragma unroll
        for (int g = 0; g < 4; ++g) {             // k16 step over seq
            // P fragments: C-layout -> A-layout identity, hi/lo split
            uint32_t pah[4], pal[4];
            {
                float a0 = s[2*g][0],   a1 = s[2*g][1];
                float a2 = s[2*g][2],   a3 = s[2*g][3];
                float a4 = s[2*g+1][0], a5 = s[2*g+1][1];
                float a6 = s[2*g+1][2], a7 = s[2*g+1][3];
                pah[0] = pack_bf16x2(a0, a1);
                pah[1] = pack_bf16x2(a2, a3);
                pah[2] = pack_bf16x2(a4, a5);
                pah[3] = pack_bf16x2(a6, a7);
                __nv_bfloat162 h;
                h = *(__nv_bfloat162*)&pah[0];
                pal[0] = pack_bf16x2(a0 - __bfloat162float(h.x), a1 - __bfloat162float(h.y));
                h = *(__nv_bfloat162*)&pah[1];
                pal[1] = pack_bf16x2(a2 - __bfloat162float(h.x), a3 - __bfloat162float(h.y));
                h = *(__nv_bfloat162*)&pah[2];
                pal[2] = pack_bf16x2(a4 - __bfloat162float(h.x), a5 - __bfloat162float(h.y));
                h = *(__nv_bfloat162*)&pah[3];
                pal[3] = pack_bf16x2(a6 - __bfloat162float(h.x), a7 - __bfloat162float(h.y));
            }
            const uint32_t ro = (uint32_t)(g * 16 + frag_row) * (APITCH * 2);
            #pragma unroll
            for (int h2 = 0; h2 < 8; ++h2) {      // n16 pair over head cols
                uint32_t co = (uint32_t)(h2 * 16 + frag_col) * 2;
                uint32_t b0, b1, b2, b3, c0, c1, c2, c3;
                ldsm_x4_t(b0, b1, b2, b3, VhB + ro + co);
                ldsm_x4_t(c0, c1, c2, c3, VlB + ro + co);
                mma_bf16(o[2*h2],   pah, b0, b1);
                mma_bf16(o[2*h2+1], pah, b2, b3);
                mma_bf16(o[2*h2],   pah, c0, c1);
                mma_bf16(o[2*h2+1], pah, c2, c3);
                mma_bf16(o[2*h2],   pal, b0, b1);
                mma_bf16(o[2*h2+1], pal, b2, b3);
            }
        }
    }

    // ---- Epilogue: normalize, write fp32 ----
    const float inv0 = 1.0f / l0;
    const float inv1 = 1.0f / l1;
    float* op = out + (size_t)b * TT * HH;
    #pragma unroll
    for (int j = 0; j < 16; ++j) {
        int cc = j * 8 + (lane & 3) * 2;
        *(float2*)&op[(size_t)r0g * HH + cc] = make_float2(o[j][0] * inv0, o[j][1] * inv0);
        *(float2*)&op[(size_t)r1g * HH + cc] = make_float2(o[j][2] * inv1, o[j][3] * inv1);
    }
}

// ---------------------------------------------------------------------------
extern "C" void kernel_launch(void* const* d_in, const int* in_sizes, int n_in,
                              void* d_out, int out_size)
{
    const float* x  = (const float*)d_in[0];
    const float* Wq = (const float*)d_in[1];
    const float* Wk = (const float*)d_in[2];
    const float* Wv = (const float*)d_in[3];
    float* out = (float*)d_out;

    // Split inputs into bf16 hi/lo
    split_x_kernel<<<MM * DD / 4 / 256, 256>>>((const float4*)x);
    split_w_kernel<<<3 * DD * HH / 256, 256>>>(Wq, Wk, Wv);

    // QKV projection on tensor cores (mma.sync bf16-split)
    dim3 gm(MM / 128, 3);
    qkv_mma_kernel<<<gm, 256>>>();

    // Attention on tensor cores
    cudaFuncSetAttribute(attn_kernel,
                         cudaFuncAttributeMaxDynamicSharedMemorySize, ATT_SMEM);
    attn_kernel<<<BB * (TT / 64), 128, ATT_SMEM>>>(out);
}

// round 9
// speedup vs baseline: 2.4360x; 1.5458x over previous
#include <cuda_runtime.h>
#include <cuda_bf16.h>
#include <cstdint>
#include <math.h>

// Problem constants
#define BB 8
#define TT 2048
#define DD 1024
#define HH 128
#define MM (BB*TT)

// q scale includes softmax 1/sqrt(128) AND log2(e) for base-2 softmax
#define QSCALE 0.12751739641379968f

// Scratch: Q/K/V as bf16 hi/lo splits (scale folded into Q)
__device__ __nv_bfloat16 g_qh[MM*HH];
__device__ __nv_bfloat16 g_ql[MM*HH];
__device__ __nv_bfloat16 g_kh[MM*HH];
__device__ __nv_bfloat16 g_kl[MM*HH];
__device__ __nv_bfloat16 g_vh[MM*HH];
__device__ __nv_bfloat16 g_vl[MM*HH];
__device__ __nv_bfloat16 g_wh[3*HH*DD]; // W hi, transposed [w][n][k]
__device__ __nv_bfloat16 g_wl[3*HH*DD]; // W lo, transposed

// ---------------------------------------------------------------------------
// PTX helpers
// ---------------------------------------------------------------------------
__device__ __forceinline__ uint32_t smem_u32(const void* p) {
    uint32_t a;
    asm("{ .reg .u64 t; cvta.to.shared.u64 t, %1; cvt.u32.u64 %0, t; }"
        : "=r"(a) : "l"(p));
    return a;
}

__device__ __forceinline__ void ldsm_x4(uint32_t& r0, uint32_t& r1,
                                        uint32_t& r2, uint32_t& r3,
                                        uint32_t addr) {
    asm volatile("ldmatrix.sync.aligned.m8n8.x4.shared.b16 {%0,%1,%2,%3}, [%4];"
                 : "=r"(r0), "=r"(r1), "=r"(r2), "=r"(r3) : "r"(addr));
}

__device__ __forceinline__ void ldsm_x4_t(uint32_t& r0, uint32_t& r1,
                                          uint32_t& r2, uint32_t& r3,
                                          uint32_t addr) {
    asm volatile("ldmatrix.sync.aligned.m8n8.x4.trans.shared.b16 {%0,%1,%2,%3}, [%4];"
                 : "=r"(r0), "=r"(r1), "=r"(r2), "=r"(r3) : "r"(addr));
}

__device__ __forceinline__ void mma_bf16(float* c, const uint32_t* a,
                                         uint32_t b0, uint32_t b1) {
    asm volatile(
        "mma.sync.aligned.m16n8k16.row.col.f32.bf16.bf16.f32 "
        "{%0,%1,%2,%3}, {%4,%5,%6,%7}, {%8,%9}, {%0,%1,%2,%3};"
        : "+f"(c[0]), "+f"(c[1]), "+f"(c[2]), "+f"(c[3])
        : "r"(a[0]), "r"(a[1]), "r"(a[2]), "r"(a[3]), "r"(b0), "r"(b1));
}

__device__ __forceinline__ uint32_t pack_bf16x2(float a, float b) {
    __nv_bfloat162 p = __halves2bfloat162(__float2bfloat16(a), __float2bfloat16(b));
    return *(uint32_t*)&p;
}

__device__ __forceinline__ void cp_async16(uint32_t dst, const void* src) {
    asm volatile("cp.async.cg.shared.global [%0], [%1], 16;"
                 :: "r"(dst), "l"(src) : "memory");
}
__device__ __forceinline__ void cp_commit() {
    asm volatile("cp.async.commit_group;" ::: "memory");
}
template<int N>
__device__ __forceinline__ void cp_wait() {
    asm volatile("cp.async.wait_group %0;" :: "n"(N) : "memory");
}

// ---------------------------------------------------------------------------
// Kernel 0: split + transpose W -> Wh_t, Wl_t  ([w][n][k], bf16)
// ---------------------------------------------------------------------------
__global__ __launch_bounds__(256) void split_w_kernel(
    const float* __restrict__ Wq,
    const float* __restrict__ Wk,
    const float* __restrict__ Wv)
{
    int i = blockIdx.x * 256 + threadIdx.x;   // < 3*DD*HH
    int widx = i / (DD * HH);
    int rem  = i - widx * DD * HH;
    int k = rem / HH;
    int n = rem % HH;
    const float* W = (widx == 0) ? Wq : (widx == 1) ? Wk : Wv;
    float v = W[k * HH + n];
    __nv_bfloat16 h = __float2bfloat16(v);
    __nv_bfloat16 l = __float2bfloat16(v - __bfloat162float(h));
    size_t dst = (size_t)widx * HH * DD + (size_t)n * DD + k;
    g_wh[dst] = h;
    g_wl[dst] = l;
}

// ---------------------------------------------------------------------------
// Kernel 1: merged QKV GEMM on mma.sync bf16-split (3 products).
// Grid 256 (M tiles of 64 rows); 256 threads = 8 warps: 4(M m16) x 2(N n64).
// X fp32 loaded once per CTA and split to hi/lo bf16 during smem staging.
// All 3 weights computed per CTA (X reuse); epilogue writes bf16 hi/lo QKV.
// ---------------------------------------------------------------------------
#define GP 40
#define G_SA_H 0
#define G_SA_L (64*GP)
#define G_SB   (2*64*GP)             // 6 tiles of 128*GP: [w][split]
#define GEMM_SMEM_ELEMS (2*64*GP + 6*128*GP)
#define GEMM_SMEM_BYTES (GEMM_SMEM_ELEMS * 2)

__global__ __launch_bounds__(256, 2) void qkv_mma_kernel(const float* __restrict__ x)
{
    extern __shared__ __nv_bfloat16 gsm[];
    __nv_bfloat16* sAh = gsm + G_SA_H;
    __nv_bfloat16* sAl = gsm + G_SA_L;

    const int tid  = threadIdx.x;
    const int wid  = tid >> 5;
    const int lane = tid & 31;
    const int m0   = blockIdx.x * 64;

    const float* xp = x + (size_t)m0 * DD;

    const int warp_m0 = (wid & 3) * 16;
    const int warp_n0 = (wid >> 2) * 64;

    float acc[3][8][4];
    #pragma unroll
    for (int w = 0; w < 3; ++w)
        #pragma unroll
        for (int j = 0; j < 8; ++j)
            #pragma unroll
            for (int e = 0; e < 4; ++e) acc[w][j][e] = 0.f;

    const int arow = tid >> 2;
    const int aseg = (tid & 3) * 8;
    const uint32_t aBaseH = smem_u32(sAh);
    const uint32_t aBaseL = smem_u32(sAl);
    const uint32_t bBase0 = smem_u32(gsm + G_SB);
    const int frag_row = lane & 15;
    const int frag_col = (lane >> 4) * 8;

    for (int c = 0; c < 32; ++c) {
        const int k0 = c * 32;

        // --- Stage A: load fp32, split hi/lo, store bf16 ---
        {
            float4 u0 = *(const float4*)&xp[(size_t)arow * DD + k0 + aseg];
            float4 u1 = *(const float4*)&xp[(size_t)arow * DD + k0 + aseg + 4];
            float f[8] = {u0.x, u0.y, u0.z, u0.w, u1.x, u1.y, u1.z, u1.w};
            uint32_t hh[4], ll[4];
            #pragma unroll
            for (int e = 0; e < 4; ++e) {
                float a = f[2*e], b = f[2*e+1];
                __nv_bfloat16 ha = __float2bfloat16(a);
                __nv_bfloat16 hb = __float2bfloat16(b);
                hh[e] = pack_bf16x2(a, b);
                ll[e] = pack_bf16x2(a - __bfloat162float(ha),
                                    b - __bfloat162float(hb));
            }
            *(uint4*)&sAh[arow * GP + aseg] = *(uint4*)hh;
            *(uint4*)&sAl[arow * GP + aseg] = *(uint4*)ll;
        }
        // --- Stage B: 3 weights x 2 splits, bf16 direct ---
        #pragma unroll
        for (int w = 0; w < 3; ++w) {
            const __nv_bfloat16* wh = g_wh + (size_t)w * HH * DD;
            const __nv_bfloat16* wl = g_wl + (size_t)w * HH * DD;
            __nv_bfloat16* sBh = gsm + G_SB + (w * 2    ) * 128 * GP;
            __nv_bfloat16* sBl = gsm + G_SB + (w * 2 + 1) * 128 * GP;
            #pragma unroll
            for (int p = 0; p < 2; ++p) {
                int i = tid + p * 256;
                int row = i >> 2, seg = (i & 3) * 8;
                size_t gs = (size_t)row * DD + k0 + seg;
                *(uint4*)&sBh[row * GP + seg] = *(const uint4*)&wh[gs];
                *(uint4*)&sBl[row * GP + seg] = *(const uint4*)&wl[gs];
            }
        }
        __syncthreads();

        #pragma unroll
        for (int s = 0; s < 2; ++s) {
            const uint32_t colOff = (uint32_t)(s * 16 + frag_col) * 2;
            uint32_t ah[4], al[4];
            {
                uint32_t ro = (uint32_t)(warp_m0 + frag_row) * (GP * 2);
                ldsm_x4(ah[0], ah[1], ah[2], ah[3], aBaseH + ro + colOff);
                ldsm_x4(al[0], al[1], al[2], al[3], aBaseL + ro + colOff);
            }
            #pragma unroll
            for (int w = 0; w < 3; ++w) {
                const uint32_t bh_base = bBase0 + (w * 2    ) * 128 * GP * 2;
                const uint32_t bl_base = bBase0 + (w * 2 + 1) * 128 * GP * 2;
                #pragma unroll
                for (int g = 0; g < 4; ++g) {
                    uint32_t ro = (uint32_t)(warp_n0 + g * 16 + frag_row) * (GP * 2);
                    uint32_t b0, b1, b2, b3, c0, c1, c2, c3;
                    ldsm_x4(b0, b1, b2, b3, bh_base + ro + colOff);
                    ldsm_x4(c0, c1, c2, c3, bl_base + ro + colOff);
                    mma_bf16(acc[w][2*g],   ah, b0, b2);
                    mma_bf16(acc[w][2*g+1], ah, b1, b3);
                    mma_bf16(acc[w][2*g],   ah, c0, c2);
                    mma_bf16(acc[w][2*g+1], ah, c1, c3);
                    mma_bf16(acc[w][2*g],   al, b0, b2);
                    mma_bf16(acc[w][2*g+1], al, b1, b3);
                }
            }
        }
        __syncthreads();
    }

    // Epilogue: split fp32 accum -> bf16 hi/lo per weight
    #pragma unroll
    for (int w = 0; w < 3; ++w) {
        __nv_bfloat16* outh = (w == 0) ? g_qh : (w == 1) ? g_kh : g_vh;
        __nv_bfloat16* outl = (w == 0) ? g_ql : (w == 1) ? g_kl : g_vl;
        const float sc = (w == 0) ? QSCALE : 1.0f;
        int rr = m0 + warp_m0 + (lane >> 2);
        #pragma unroll
        for (int j = 0; j < 8; ++j) {
            int cc = warp_n0 + j * 8 + (lane & 3) * 2;
            #pragma unroll
            for (int half = 0; half < 2; ++half) {
                float v0 = acc[w][j][half * 2]     * sc;
                float v1 = acc[w][j][half * 2 + 1] * sc;
                __nv_bfloat16 h0 = __float2bfloat16(v0);
                __nv_bfloat16 h1 = __float2bfloat16(v1);
                __nv_bfloat16 l0 = __float2bfloat16(v0 - __bfloat162float(h0));
                __nv_bfloat16 l1 = __float2bfloat16(v1 - __bfloat162float(h1));
                size_t off = (size_t)(rr + half * 8) * HH + cc;
                *(__nv_bfloat162*)&outh[off] = __halves2bfloat162(h0, h1);
                *(__nv_bfloat162*)&outl[off] = __halves2bfloat162(l0, l1);
            }
        }
    }
}

// ---------------------------------------------------------------------------
// Kernel 2: causal flash attention on tensor cores, cp.async pipelined.
// Grid 256 = 8 batches x 32 Q tiles (64 rows), heavy tiles first; 128 threads.
// K double-buffered (2 stages), V single buffer; base-2 online softmax.
// ---------------------------------------------------------------------------
#define APITCH 136
#define TILE_E (64 * APITCH)                  // elems per tile
#define ATT_SMEM_BYTES (6 * TILE_E * 2)       // Kh0,Kl0,Kh1,Kl1,Vh,Vl

__global__ __launch_bounds__(128, 2) void attn_kernel(float* __restrict__ out)
{
    extern __shared__ __nv_bfloat16 smb[];
    const uint32_t smB = smem_u32(smb);
    const uint32_t KhB[2] = {smB,              smB + 2u*TILE_E*2u};
    const uint32_t KlB[2] = {smB + TILE_E*2u,  smB + 3u*TILE_E*2u};
    const uint32_t VhB = smB + 4u*TILE_E*2u;
    const uint32_t VlB = smB + 5u*TILE_E*2u;

    const int bid   = blockIdx.x;
    const int qtile = 31 - (bid >> 3);
    const int b     = bid & 7;
    const int row0  = qtile * 64;

    const __nv_bfloat16* qhp = g_qh + (size_t)b * TT * HH;
    const __nv_bfloat16* qlp = g_ql + (size_t)b * TT * HH;
    const __nv_bfloat16* khp = g_kh + (size_t)b * TT * HH;
    const __nv_bfloat16* klp = g_kl + (size_t)b * TT * HH;
    const __nv_bfloat16* vhp = g_vh + (size_t)b * TT * HH;
    const __nv_bfloat16* vlp = g_vl + (size_t)b * TT * HH;

    const int tid  = threadIdx.x;
    const int warp = tid >> 5;
    const int lane = tid & 31;
    const int frag_row = lane & 15;
    const int frag_col = (lane >> 4) * 8;

    const int crow = tid >> 4;           // 0..7
    const int cseg = (tid & 15) * 8;     // 0..120

    // ---- Stage Q into Kh0/Kl0, grab fragments, then release buffer ----
    for (int i = tid; i < 64 * 16; i += 128) {
        int r = i >> 4, seg = (i & 15) * 8;
        *(uint4*)&smb[0*TILE_E + r * APITCH + seg] =
            *(const uint4*)&qhp[(size_t)(row0 + r) * HH + seg];
        *(uint4*)&smb[1*TILE_E + r * APITCH + seg] =
            *(const uint4*)&qlp[(size_t)(row0 + r) * HH + seg];
    }
    __syncthreads();

    uint32_t qh[8][4], ql[8][4];
    {
        uint32_t ro = (uint32_t)(warp * 16 + frag_row) * (APITCH * 2);
        #pragma unroll
        for (int g = 0; g < 8; ++g) {
            uint32_t co = (uint32_t)(g * 16 + frag_col) * 2;
            ldsm_x4(qh[g][0], qh[g][1], qh[g][2], qh[g][3], KhB[0] + ro + co);
            ldsm_x4(ql[g][0], ql[g][1], ql[g][2], ql[g][3], KlB[0] + ro + co);
        }
    }
    __syncthreads();   // all warps done reading Q from buffer 0

    // issue K(0) into buf0, then V(0)  (two commit groups)
    {
        #pragma unroll
        for (int r8 = 0; r8 < 8; ++r8) {
            int r = crow + r8 * 8;
            size_t gs = (size_t)r * HH + cseg;
            uint32_t ds = (uint32_t)(r * APITCH + cseg) * 2;
            cp_async16(KhB[0] + ds, khp + gs);
            cp_async16(KlB[0] + ds, klp + gs);
        }
        cp_commit();
        #pragma unroll
        for (int r8 = 0; r8 < 8; ++r8) {
            int r = crow + r8 * 8;
            size_t gs = (size_t)r * HH + cseg;
            uint32_t ds = (uint32_t)(r * APITCH + cseg) * 2;
            cp_async16(VhB + ds, vhp + gs);
            cp_async16(VlB + ds, vlp + gs);
        }
        cp_commit();
    }

    float o[16][4];
    #pragma unroll
    for (int j = 0; j < 16; ++j)
        #pragma unroll
        for (int e = 0; e < 4; ++e) o[j][e] = 0.f;
    float m0 = -1e30f, m1 = -1e30f, l0 = 0.f, l1 = 0.f;

    const int r0g = row0 + warp * 16 + (lane >> 2);
    const int r1g = r0g + 8;

    for (int kt = 0; kt <= qtile; ++kt) {
        const int cur = kt & 1;
        const int nxt = cur ^ 1;

        cp_wait<1>();        // K(kt) ready (all but newest group)
        __syncthreads();

        // prefetch K(kt+1) into the other buffer (clamped on last iter)
        {
            int knr = (kt < qtile) ? (kt + 1) * 64 : kt * 64;
            #pragma unroll
            for (int r8 = 0; r8 < 8; ++r8) {
                int r = crow + r8 * 8;
                size_t gs = (size_t)(knr + r) * HH + cseg;
                uint32_t ds = (uint32_t)(r * APITCH + cseg) * 2;
                cp_async16(KhB[nxt] + ds, khp + gs);
                cp_async16(KlB[nxt] + ds, klp + gs);
            }
            cp_commit();
        }

        // ---- S = Q K^T ----
        float s[8][4];
        #pragma unroll
        for (int j = 0; j < 8; ++j)
            #pragma unroll
            for (int e = 0; e < 4; ++e) s[j][e] = 0.f;

        #pragma unroll
        for (int g = 0; g < 8; ++g) {
            const uint32_t co = (uint32_t)(g * 16 + frag_col) * 2;
            #pragma unroll
            for (int n = 0; n < 4; ++n) {
                uint32_t ro = (uint32_t)(n * 16 + frag_row) * (APITCH * 2);
                uint32_t b0, b1, b2, b3, c0, c1, c2, c3;
                ldsm_x4(b0, b1, b2, b3, KhB[cur] + ro + co);
                ldsm_x4(c0, c1, c2, c3, KlB[cur] + ro + co);
                mma_bf16(s[2*n],   qh[g], b0, b2);
                mma_bf16(s[2*n+1], qh[g], b1, b3);
                mma_bf16(s[2*n],   qh[g], c0, c2);
                mma_bf16(s[2*n+1], qh[g], c1, c3);
                mma_bf16(s[2*n],   ql[g], b0, b2);
                mma_bf16(s[2*n+1], ql[g], b1, b3);
            }
        }

        // ---- causal mask (diagonal tile) ----
        const int kr0 = kt * 64;
        if (kt == qtile) {
            const int c0 = kr0 + (lane & 3) * 2;
            #pragma unroll
            for (int j = 0; j < 8; ++j) {
                int cg = c0 + j * 8;
                if (cg     > r0g) s[j][0] = -1e30f;
                if (cg + 1 > r0g) s[j][1] = -1e30f;
                if (cg     > r1g) s[j][2] = -1e30f;
                if (cg + 1 > r1g) s[j][3] = -1e30f;
            }
        }

        // ---- online softmax (base 2) ----
        float mx0 = -1e30f, mx1 = -1e30f;
        #pragma unroll
        for (int j = 0; j < 8; ++j) {
            mx0 = fmaxf(mx0, fmaxf(s[j][0], s[j][1]));
            mx1 = fmaxf(mx1, fmaxf(s[j][2], s[j][3]));
        }
        mx0 = fmaxf(mx0, __shfl_xor_sync(0xffffffffu, mx0, 1));
        mx0 = fmaxf(mx0, __shfl_xor_sync(0xffffffffu, mx0, 2));
        mx1 = fmaxf(mx1, __shfl_xor_sync(0xffffffffu, mx1, 1));
        mx1 = fmaxf(mx1, __shfl_xor_sync(0xffffffffu, mx1, 2));
        const float nm0 = fmaxf(m0, mx0);
        const float nm1 = fmaxf(m1, mx1);
        float sum0 = 0.f, sum1 = 0.f;
        #pragma unroll
        for (int j = 0; j < 8; ++j) {
            s[j][0] = exp2f(s[j][0] - nm0);
            s[j][1] = exp2f(s[j][1] - nm0);
            s[j][2] = exp2f(s[j][2] - nm1);
            s[j][3] = exp2f(s[j][3] - nm1);
            sum0 += s[j][0] + s[j][1];
            sum1 += s[j][2] + s[j][3];
        }
        sum0 += __shfl_xor_sync(0xffffffffu, sum0, 1);
        sum0 += __shfl_xor_sync(0xffffffffu, sum0, 2);
        sum1 += __shfl_xor_sync(0xffffffffu, sum1, 1);
        sum1 += __shfl_xor_sync(0xffffffffu, sum1, 2);
        const float cr0 = exp2f(m0 - nm0);
        const float cr1 = exp2f(m1 - nm1);
        l0 = l0 * cr0 + sum0;
        l1 = l1 * cr1 + sum1;
        m0 = nm0; m1 = nm1;
        #pragma unroll
        for (int j = 0; j < 16; ++j) {
            o[j][0] *= cr0; o[j][1] *= cr0;
            o[j][2] *= cr1; o[j][3] *= cr1;
        }

        cp_wait<1>();        // V(kt) ready (all but newest = K prefetch)
        __syncthreads();

        // ---- O += P V ----
        #pragma unroll
        for (int g = 0; g < 4; ++g) {
            uint32_t pah[4], pal[4];
            {
                float a0 = s[2*g][0],   a1 = s[2*g][1];
                float a2 = s[2*g][2],   a3 = s[2*g][3];
                float a4 = s[2*g+1][0], a5 = s[2*g+1][1];
                float a6 = s[2*g+1][2], a7 = s[2*g+1][3];
                pah[0] = pack_bf16x2(a0, a1);
                pah[1] = pack_bf16x2(a2, a3);
                pah[2] = pack_bf16x2(a4, a5);
                pah[3] = pack_bf16x2(a6, a7);
                __nv_bfloat162 h;
                h = *(__nv_bfloat162*)&pah[0];
                pal[0] = pack_bf16x2(a0 - __bfloat162float(h.x), a1 - __bfloat162float(h.y));
                h = *(__nv_bfloat162*)&pah[1];
                pal[1] = pack_bf16x2(a2 - __bfloat162float(h.x), a3 - __bfloat162float(h.y));
                h = *(__nv_bfloat162*)&pah[2];
                pal[2] = pack_bf16x2(a4 - __bfloat162float(h.x), a5 - __bfloat162float(h.y));
                h = *(__nv_bfloat162*)&pah[3];
                pal[3] = pack_bf16x2(a6 - __bfloat162float(h.x), a7 - __bfloat162float(h.y));
            }
            const uint32_t ro = (uint32_t)(g * 16 + frag_row) * (APITCH * 2);
            #pragma unroll
            for (int h2 = 0; h2 < 8; ++h2) {
                uint32_t co = (uint32_t)(h2 * 16 + frag_col) * 2;
                uint32_t b0, b1, b2, b3, c0, c1, c2, c3;
                ldsm_x4_t(b0, b1, b2, b3, VhB + ro + co);
                ldsm_x4_t(c0, c1, c2, c3, VlB + ro + co);
                mma_bf16(o[2*h2],   pah, b0, b1);
                mma_bf16(o[2*h2+1], pah, b2, b3);
                mma_bf16(o[2*h2],   pah, c0, c1);
                mma_bf16(o[2*h2+1], pah, c2, c3);
                mma_bf16(o[2*h2],   pal, b0, b1);
                mma_bf16(o[2*h2+1], pal, b2, b3);
            }
        }

        __syncthreads();     // all warps done reading V

        // prefetch V(kt+1) (clamped on last iter)
        {
            int vnr = (kt < qtile) ? (kt + 1) * 64 : kt * 64;
            #pragma unroll
            for (int r8 = 0; r8 < 8; ++r8) {
                int r = crow + r8 * 8;
                size_t gs = (size_t)(vnr + r) * HH + cseg;
                uint32_t ds = (uint32_t)(r * APITCH + cseg) * 2;
                cp_async16(VhB + ds, vhp + gs);
                cp_async16(VlB + ds, vlp + gs);
            }
            cp_commit();
        }
    }

    cp_wait<0>();

    // ---- Epilogue ----
    const float inv0 = 1.0f / l0;
    const float inv1 = 1.0f / l1;
    float* op = out + (size_t)b * TT * HH;
    #pragma unroll
    for (int j = 0; j < 16; ++j) {
        int cc = j * 8 + (lane & 3) * 2;
        *(float2*)&op[(size_t)r0g * HH + cc] = make_float2(o[j][0] * inv0, o[j][1] * inv0);
        *(float2*)&op[(size_t)r1g * HH + cc] = make_float2(o[j][2] * inv1, o[j][3] * inv1);
    }
}

// ---------------------------------------------------------------------------
extern "C" void kernel_launch(void* const* d_in, const int* in_sizes, int n_in,
                              void* d_out, int out_size)
{
    const float* x  = (const float*)d_in[0];
    const float* Wq = (const float*)d_in[1];
    const float* Wk = (const float*)d_in[2];
    const float* Wv = (const float*)d_in[3];
    float* out = (float*)d_out;

    split_w_kernel<<<3 * DD * HH / 256, 256>>>(Wq, Wk, Wv);

    cudaFuncSetAttribute(qkv_mma_kernel,
                         cudaFuncAttributeMaxDynamicSharedMemorySize, GEMM_SMEM_BYTES);
    qkv_mma_kernel<<<MM / 64, 256, GEMM_SMEM_BYTES>>>(x);

    cudaFuncSetAttribute(attn_kernel,
                         cudaFuncAttributeMaxDynamicSharedMemorySize, ATT_SMEM_BYTES);
    attn_kernel<<<BB * (TT / 64), 128, ATT_SMEM_BYTES>>>(out);
}